// round 15
// baseline (speedup 1.0000x reference)
#include <cuda_runtime.h>
#include <cuda_bf16.h>
#include <float.h>
#include <cstdint>

#define NROWS 8192
#define DIM   128
#define NT    64
#define NPAIR (NT*(NT+1)/2)   // 2080 triangular tile pairs
#define GRID_PERS 148
#define MARGIN_F 0.5f

// smem map (tcgen05 path)
#define CTRL_TMEM   0
#define CTRL_MBTMA  8
#define CTRL_MBMMA1 16
#define CTRL_MBMMA2 24
#define CTRL_SQI    128
#define CTRL_SQJ    640
#define CTRL_LABI   1152
#define CTRL_LABJ   1664
#define REGION0     4096
#define REG_SZ      32768
#define SMEM_TOTAL  (REGION0 + 4 * REG_SZ)   // 135168 B

// idesc kind::f16 cg1: F32 out, BF16 a/b, N=128, M=128
#define MMA_IDESC 0x8200490u

// fallback (plain sm_103) FFMA tiling constants
#define BK    32
#define LDA2  130
#define LDB   132

#if defined(__CUDA_ARCH_FEAT_SM103_ALL) || defined(__CUDA_ARCH_FEAT_SM100_ALL)
#define HAS_TCGEN05 1
#else
#define HAS_TCGEN05 0
#endif

typedef unsigned long long ull;

__device__ int   g_pos[NROWS];
__device__ int   g_neg[NROWS];
__device__ float g_sq[NROWS];
__device__ float g_sum;
__device__ int   g_cnt;
// Pre-split bf16 tiles in blocked SW128 layout: 64 tiles x 32KB each.
__device__ __align__(128) ull g_hi[NT * 4096];
__device__ __align__(128) ull g_lo[NT * 4096];

__device__ __forceinline__ int f2ord(float f) {
    int i = __float_as_int(f);
    return i >= 0 ? i : i ^ 0x7FFFFFFF;
}
__device__ __forceinline__ float ord2f(int i) {
    return __int_as_float(i >= 0 ? i : i ^ 0x7FFFFFFF);
}
__device__ __forceinline__ ull pack4(unsigned short a, unsigned short b,
                                     unsigned short c, unsigned short d) {
    return (ull)a | ((ull)b << 16) | ((ull)c << 32) | ((ull)d << 48);
}
__device__ __forceinline__ void split2(float x, unsigned short &h, unsigned short &l) {
    __nv_bfloat16 a = __float2bfloat16(x);
    __nv_bfloat16 b = __float2bfloat16(x - __bfloat162float(a));
    h = __bfloat16_as_ushort(a);
    l = __bfloat16_as_ushort(b);
}

// ---------------------------------------------------------------------------
// Kernel 1 (merged): 2-way bf16 split of X into pre-swizzled blocked-SW128
// tiles AND row squared norms + accumulator init. Warp-per-row layout: for
// each strided iteration, one warp covers one row (lane = 4-col group).
// ---------------------------------------------------------------------------
__global__ void split_kernel(const float* __restrict__ X) {
    const int t = blockIdx.x;
    const float* src = X + (size_t)t * 128 * DIM;
    char* hi = (char*)g_hi + (size_t)t * REG_SZ;
    char* lo = (char*)g_lo + (size_t)t * REG_SZ;
    if (t == 0 && threadIdx.x == 0) { g_sum = 0.0f; g_cnt = 0; }
    for (int f = threadIdx.x; f < 4096; f += 256) {
        int row = f >> 5, c4 = f & 31;
        float4 v = reinterpret_cast<const float4*>(src + (size_t)row * DIM)[c4];
        int col  = c4 * 4;
        int boff = ((row >> 3) + (col >> 6) * 16) * 1024 + (row & 7) * 128 + (col & 63) * 2;
        int sw   = boff ^ ((boff >> 3) & 0x70);
        unsigned short h0,l0, h1,l1, h2,l2, h3,l3;
        split2(v.x, h0, l0); split2(v.y, h1, l1);
        split2(v.z, h2, l2); split2(v.w, h3, l3);
        *(ull*)(hi + sw) = pack4(h0, h1, h2, h3);
        *(ull*)(lo + sw) = pack4(l0, l1, l2, l3);
        // Row norm: whole warp holds this row (lane == c4).
        float s = v.x * v.x + v.y * v.y + v.z * v.z + v.w * v.w;
        #pragma unroll
        for (int o = 16; o; o >>= 1) s += __shfl_xor_sync(0xffffffffu, s, o);
        if (c4 == 0) {
            int grow = t * 128 + row;
            g_sq[grow]  = s;
            g_pos[grow] = f2ord(-FLT_MAX);
            g_neg[grow] = f2ord(FLT_MAX);
        }
    }
}

#if HAS_TCGEN05
// ============================ tcgen05 path ==================================
__device__ __forceinline__ uint32_t smem_u32(const void* p) {
    uint32_t a;
    asm("{ .reg .u64 t; cvta.to.shared.u64 t, %1; cvt.u32.u64 %0, t; }" : "=r"(a) : "l"(p));
    return a;
}
__device__ __forceinline__ uint32_t elect_one_pred() {
    uint32_t p;
    asm volatile("{ .reg .pred p; elect.sync _|p, 0xFFFFFFFF; selp.b32 %0, 1, 0, p; }" : "=r"(p));
    return p;
}
#define TCGEN05_ALLOC(smaddr, n) \
    asm volatile("tcgen05.alloc.cta_group::1.sync.aligned.shared::cta.b32 [%0], %1;" \
                 :: "r"((uint32_t)(smaddr)), "r"((uint32_t)(n)) : "memory")
#define TCGEN05_DEALLOC(tm, n) \
    asm volatile("tcgen05.dealloc.cta_group::1.sync.aligned.b32 %0, %1;" :: "r"(tm), "r"((uint32_t)(n)))
#define TCGEN05_COMMIT(mb) \
    asm volatile("tcgen05.commit.cta_group::1.mbarrier::arrive::one.shared::cluster.b64 [%0];" \
                 :: "r"((uint32_t)(mb)) : "memory")
#define TCGEN05_FENCE_AFTER()  asm volatile("tcgen05.fence::after_thread_sync;" ::: "memory")
#define TCGEN05_FENCE_BEFORE() asm volatile("tcgen05.fence::before_thread_sync;" ::: "memory")
#define TCGEN05_WAIT_LD()      asm volatile("tcgen05.wait::ld.sync.aligned;" ::: "memory")
#define MBARRIER_INIT(mb, n) \
    asm volatile("mbarrier.init.shared.b64 [%0], %1;" :: "r"((uint32_t)(mb)), "r"((uint32_t)(n)) : "memory")
#define MBARRIER_INVAL(mb) \
    asm volatile("mbarrier.inval.shared.b64 [%0];" :: "r"((uint32_t)(mb)) : "memory")
#define MBARRIER_EXPECT_TX(mb, bytes) \
    asm volatile("mbarrier.arrive.expect_tx.shared.b64 _, [%0], %1;" \
                 :: "r"((uint32_t)(mb)), "r"((uint32_t)(bytes)) : "memory")
#define MBARRIER_WAIT_PARITY(mb, ph) do {                                        \
    uint32_t _mb = (uint32_t)(mb), _ph = (uint32_t)(ph), _done;                  \
    asm volatile("{ .reg .pred p; mbarrier.try_wait.parity.acquire.cta.shared::cta.b64 p, [%1], %2;" \
                 " selp.b32 %0, 1, 0, p; }" : "=r"(_done) : "r"(_mb), "r"(_ph) : "memory"); \
    if (!_done) {                                                                \
        asm volatile("{ .reg .pred P1; WL_%=:"                                   \
                     " mbarrier.try_wait.parity.acquire.cta.shared::cta.b64 P1, [%0], %1, 0x989680;" \
                     " @P1 bra.uni WD_%=; bra.uni WL_%=; WD_%=: }"               \
                     :: "r"(_mb), "r"(_ph) : "memory");                          \
    }                                                                            \
} while (0)
#define BULK_G2S(dst, src, bytes, mb) \
    asm volatile("cp.async.bulk.shared::cta.global.mbarrier::complete_tx::bytes [%0], [%1], %2, [%3];" \
                 :: "r"((uint32_t)(dst)), "l"(src), "r"((uint32_t)(bytes)), "r"((uint32_t)(mb)) : "memory")
#define TCGEN05_LD_32X32B_X32(r, tm) \
    asm volatile("tcgen05.ld.sync.aligned.32x32b.x32.b32 " \
        "{%0, %1, %2, %3, %4, %5, %6, %7, %8, %9, %10, %11, %12, %13, %14, %15, " \
        " %16, %17, %18, %19, %20, %21, %22, %23, %24, %25, %26, %27, %28, %29, %30, %31}, [%32];" \
        : "=r"((r)[0]),  "=r"((r)[1]),  "=r"((r)[2]),  "=r"((r)[3]), \
          "=r"((r)[4]),  "=r"((r)[5]),  "=r"((r)[6]),  "=r"((r)[7]), \
          "=r"((r)[8]),  "=r"((r)[9]),  "=r"((r)[10]), "=r"((r)[11]), \
          "=r"((r)[12]), "=r"((r)[13]), "=r"((r)[14]), "=r"((r)[15]), \
          "=r"((r)[16]), "=r"((r)[17]), "=r"((r)[18]), "=r"((r)[19]), \
          "=r"((r)[20]), "=r"((r)[21]), "=r"((r)[22]), "=r"((r)[23]), \
          "=r"((r)[24]), "=r"((r)[25]), "=r"((r)[26]), "=r"((r)[27]), \
          "=r"((r)[28]), "=r"((r)[29]), "=r"((r)[30]), "=r"((r)[31]) \
        : "r"(tm))

static constexpr uint64_t SMEM_DESC_BASE_SW128 =
    (uint64_t(2) << 61) | (uint64_t(1) << 46) | (uint64_t(64) << 32) | (uint64_t(1) << 16);
#define MAKE_SMEM_DESC(a) (SMEM_DESC_BASE_SW128 | ((uint64_t)((a) >> 4) & 0x3FFF))

__device__ __forceinline__ void mma_f16_ss(uint32_t d, uint64_t a, uint64_t b,
                                           uint32_t idesc, uint32_t accum) {
    asm volatile(
        "{ .reg .pred p; setp.ne.u32 p, %5, 0;\n\t"
        "tcgen05.mma.cta_group::1.kind::f16 [%0], %1, %2, %3, {%4, %4, %4, %4}, p; }"
        :: "r"(d), "l"(a), "l"(b), "r"(idesc), "r"(0u), "r"(accum) : "memory");
}

// One GEMM: 3 split-terms (hh, hl, lh) x 8 K-steps of 128x128x16 bf16 MMA.
__device__ __forceinline__ void issue_gemm(uint32_t d, uint64_t ah, uint64_t al,
                                           uint64_t bh, uint64_t bl) {
    const uint64_t A[3] = {ah, ah, al};
    const uint64_t B[3] = {bh, bl, bh};
    uint32_t accum = 0;
    #pragma unroll
    for (int t = 0; t < 3; t++) {
        #pragma unroll
        for (int k = 0; k < 8; k++) {
            uint64_t off = (k < 4) ? (uint64_t)(2 * k) : (uint64_t)(1024 + 2 * (k - 4));
            mma_f16_ss(d, A[t] + off, B[t] + off, MMA_IDESC, accum);
            accum = 1;
        }
    }
}

// Row-local epilogue over one 128x128 D tile (d^2 tracking, no sqrt).
__device__ __forceinline__ void process_tile(uint32_t tmem_d, int rowBaseX, int colBaseX,
                                             const float* sqRow, const int* labRow,
                                             const float* sqCol, const int* labCol,
                                             int wid, int lid) {
    const int sub = wid & 3, half = wid >> 2;
    const int r = sub * 32 + lid;
    uint32_t regs[64];
    TCGEN05_LD_32X32B_X32(regs,      tmem_d + half * 64);
    TCGEN05_LD_32X32B_X32(regs + 32, tmem_d + half * 64 + 32);
    TCGEN05_WAIT_LD();
    const float sqr = sqRow[r];
    const int   lr  = labRow[r];
    const int   gi  = rowBaseX + r;
    float pmax = -FLT_MAX, nmin = FLT_MAX;
    #pragma unroll 8
    for (int c = 0; c < 64; c++) {
        const int col = half * 64 + c;
        const float dot = __uint_as_float(regs[c]);
        float d2 = fmaxf(sqr + sqCol[col] - 2.0f * dot, 0.0f);
        const int gj = colBaseX + col;
        if (lr == labCol[col]) {
            if (gi != gj) pmax = fmaxf(pmax, d2);
        } else {
            nmin = fminf(nmin, d2);
        }
    }
    atomicMax(&g_pos[gi], f2ord(pmax));
    atomicMin(&g_neg[gi], f2ord(nmin));
}
#else
// ============================ FFMA fallback helpers =========================
__device__ __forceinline__ ull dup2(float x) {
    ull r; asm("mov.b64 %0, {%1, %1};" : "=l"(r) : "f"(x)); return r;
}
__device__ __forceinline__ void fma2(ull &d, ull a, ull b) {
    asm("fma.rn.f32x2 %0, %1, %2, %0;" : "+l"(d) : "l"(a), "l"(b));
}
__device__ __forceinline__ void unpack2(ull v, float &x, float &y) {
    asm("mov.b64 {%0, %1}, %2;" : "=f"(x), "=f"(y) : "l"(v));
}
#endif

__device__ __forceinline__ void decode_pair(int p, int &I, int &J) {
    int idx = p, i = 0, len = NT;
    while (idx >= len) { idx -= len; i++; len--; }
    I = i; J = i + idx;
}

// ---------------------------------------------------------------------------
// Kernel 2: persistent CTAs, pipelined. Each iteration: one 128x128 tile pair
// (I,J), J>=I. sm_103a: bulk-copied pre-split bf16 tiles + tcgen05 GEMM of
// D=X_I.X_J^T and D^T with SPLIT commits: epilogue(D1) overlaps MMA(D2);
// next pair's TMA flies under epilogue(D2).
// ---------------------------------------------------------------------------
__global__ __launch_bounds__(256, 1)
void pair_kernel(const float* __restrict__ X, const int* __restrict__ lab) {
    extern __shared__ char sm[];
    const int tid = threadIdx.x;

#if HAS_TCGEN05
    const uint32_t smb = smem_u32(sm);
    const int wid = tid >> 5, lid = tid & 31;

    if (wid == 0) TCGEN05_ALLOC(smb + CTRL_TMEM, 256);
    if (tid == 0) {
        MBARRIER_INIT(smb + CTRL_MBTMA, 1);
        MBARRIER_INIT(smb + CTRL_MBMMA1, 1);
        MBARRIER_INIT(smb + CTRL_MBMMA2, 1);
    }
    __syncthreads();

    uint32_t tmem;
    asm volatile("ld.shared.b32 %0, [%1];" : "=r"(tmem) : "r"(smb + CTRL_TMEM));
    const uint32_t D1 = tmem, D2 = tmem + 128;

    const uint64_t dAh = MAKE_SMEM_DESC(smb + REGION0 + 0 * REG_SZ);
    const uint64_t dAl = MAKE_SMEM_DESC(smb + REGION0 + 1 * REG_SZ);
    const uint64_t dBh = MAKE_SMEM_DESC(smb + REGION0 + 2 * REG_SZ);
    const uint64_t dBl = MAKE_SMEM_DESC(smb + REGION0 + 3 * REG_SZ);

    float* sqI = (float*)(sm + CTRL_SQI);
    float* sqJ = (float*)(sm + CTRL_SQJ);
    int*   lbI = (int*)(sm + CTRL_LABI);
    int*   lbJ = (int*)(sm + CTRL_LABJ);

    int ph_tma = 0, ph_mma = 0;

    // Prologue: issue copies for first pair.
    if (tid == 0) {
        int I0, J0; decode_pair(blockIdx.x, I0, J0);
        MBARRIER_EXPECT_TX(smb + CTRL_MBTMA, 4 * REG_SZ);
        BULK_G2S(smb + REGION0 + 0 * REG_SZ, (const void*)(g_hi + (size_t)I0 * 4096), REG_SZ, smb + CTRL_MBTMA);
        BULK_G2S(smb + REGION0 + 1 * REG_SZ, (const void*)(g_lo + (size_t)I0 * 4096), REG_SZ, smb + CTRL_MBTMA);
        BULK_G2S(smb + REGION0 + 2 * REG_SZ, (const void*)(g_hi + (size_t)J0 * 4096), REG_SZ, smb + CTRL_MBTMA);
        BULK_G2S(smb + REGION0 + 3 * REG_SZ, (const void*)(g_lo + (size_t)J0 * 4096), REG_SZ, smb + CTRL_MBTMA);
    }

    for (int p = blockIdx.x; p < NPAIR; p += GRID_PERS) {
        int I, J; decode_pair(p, I, J);
        const int rowBase = I * 128, colBase = J * 128;

        // Stage norms/labels early (CTRL region, independent of TMA/MMA;
        // loop-end __syncthreads guarantees last epilogue is done reading).
        if (tid < 128) {
            sqI[tid] = g_sq[rowBase + tid];
            sqJ[tid] = g_sq[colBase + tid];
            lbI[tid] = lab[rowBase + tid];
            lbJ[tid] = lab[colBase + tid];
        }

        // MMA issue (warp 0) after tile data lands; split commits.
        if (wid == 0) {
            MBARRIER_WAIT_PARITY(smb + CTRL_MBTMA, ph_tma);
            TCGEN05_FENCE_AFTER();
            if (elect_one_pred()) {
                issue_gemm(D1, dAh, dAl, dBh, dBl);   // X_I . X_J^T
                TCGEN05_COMMIT(smb + CTRL_MBMMA1);
                issue_gemm(D2, dBh, dBl, dAh, dAl);   // X_J . X_I^T
                TCGEN05_COMMIT(smb + CTRL_MBMMA2);
            }
        }
        ph_tma ^= 1;

        // D1 ready while D2's MMA still runs.
        MBARRIER_WAIT_PARITY(smb + CTRL_MBMMA1, ph_mma);
        __syncthreads();          // norms/labels staged & visible to all
        TCGEN05_FENCE_AFTER();
        process_tile(D1, rowBase, colBase, sqI, lbI, sqJ, lbJ, wid, lid);

        // D2 done => smem tile buffers free: prefetch next pair now.
        MBARRIER_WAIT_PARITY(smb + CTRL_MBMMA2, ph_mma);
        ph_mma ^= 1;
        if (p + GRID_PERS < NPAIR && tid == 0) {
            int In, Jn; decode_pair(p + GRID_PERS, In, Jn);
            MBARRIER_EXPECT_TX(smb + CTRL_MBTMA, 4 * REG_SZ);
            BULK_G2S(smb + REGION0 + 0 * REG_SZ, (const void*)(g_hi + (size_t)In * 4096), REG_SZ, smb + CTRL_MBTMA);
            BULK_G2S(smb + REGION0 + 1 * REG_SZ, (const void*)(g_lo + (size_t)In * 4096), REG_SZ, smb + CTRL_MBTMA);
            BULK_G2S(smb + REGION0 + 2 * REG_SZ, (const void*)(g_hi + (size_t)Jn * 4096), REG_SZ, smb + CTRL_MBTMA);
            BULK_G2S(smb + REGION0 + 3 * REG_SZ, (const void*)(g_lo + (size_t)Jn * 4096), REG_SZ, smb + CTRL_MBTMA);
        }

        TCGEN05_FENCE_AFTER();
        process_tile(D2, colBase, rowBase, sqJ, lbJ, sqI, lbI, wid, lid);
        TCGEN05_FENCE_BEFORE();
        __syncthreads();   // epilogue done before next iteration's MMA writes D
    }

    __syncthreads();
    if (tid == 0) {
        MBARRIER_INVAL(smb + CTRL_MBTMA);
        MBARRIER_INVAL(smb + CTRL_MBMMA1);
        MBARRIER_INVAL(smb + CTRL_MBMMA2);
    }
    __syncthreads();
    if (wid == 0) TCGEN05_DEALLOC(tmem, 256);

#else
    // -------- f32x2 FFMA fallback (persistent, d^2 tracking) ----------------
    ull*   As2 = (ull*)sm;                        // [BK][LDA2]
    float* Bs  = (float*)(As2 + BK * LDA2);       // [BK][LDB]
    const int tx = tid & 15, ty = tid >> 4;
    const int m0 = ty * 8, n0 = tx * 8;

    for (int p = blockIdx.x; p < NPAIR; p += GRID_PERS) {
        int I, J; decode_pair(p, I, J);
        const int rowBase = I * 128, colBase = J * 128;

        ull acc[8][4];
        #pragma unroll
        for (int mi = 0; mi < 8; mi++)
            #pragma unroll
            for (int nj = 0; nj < 4; nj++) acc[mi][nj] = 0ull;

        for (int kb = 0; kb < DIM; kb += BK) {
            __syncthreads();
            for (int i = tid; i < 128 * (BK / 4); i += 256) {
                int r = i >> 3, c4 = i & 7;
                float4 v = reinterpret_cast<const float4*>(
                    X + (size_t)(rowBase + r) * DIM + kb)[c4];
                int k = c4 * 4;
                As2[(k + 0) * LDA2 + r] = dup2(v.x);
                As2[(k + 1) * LDA2 + r] = dup2(v.y);
                As2[(k + 2) * LDA2 + r] = dup2(v.z);
                As2[(k + 3) * LDA2 + r] = dup2(v.w);
            }
            for (int i = tid; i < 128 * (BK / 4); i += 256) {
                int n = i >> 3, c4 = i & 7;
                float4 v = reinterpret_cast<const float4*>(
                    X + (size_t)(colBase + n) * DIM + kb)[c4];
                int k = c4 * 4;
                Bs[(k + 0) * LDB + n] = v.x;
                Bs[(k + 1) * LDB + n] = v.y;
                Bs[(k + 2) * LDB + n] = v.z;
                Bs[(k + 3) * LDB + n] = v.w;
            }
            __syncthreads();
            #pragma unroll 8
            for (int k = 0; k < BK; k++) {
                const ull* arow = &As2[k * LDA2 + m0];
                const ull* brow = (const ull*)&Bs[k * LDB + n0];
                ull A2[8], B2[4];
                #pragma unroll
                for (int t = 0; t < 8; t++) A2[t] = arow[t];
                #pragma unroll
                for (int t = 0; t < 4; t++) B2[t] = brow[t];
                #pragma unroll
                for (int mi = 0; mi < 8; mi++)
                    #pragma unroll
                    for (int nj = 0; nj < 4; nj++)
                        fma2(acc[mi][nj], A2[mi], B2[nj]);
            }
        }

        float sqi[8]; int li[8]; float sqj[8]; int lj[8];
        #pragma unroll
        for (int t = 0; t < 8; t++) {
            sqi[t] = g_sq[rowBase + m0 + t];  li[t] = lab[rowBase + m0 + t];
            sqj[t] = g_sq[colBase + n0 + t];  lj[t] = lab[colBase + n0 + t];
        }
        float posmax[8], negmin[8], colpos[8], colneg[8];
        #pragma unroll
        for (int t = 0; t < 8; t++) {
            posmax[t] = -FLT_MAX; negmin[t] = FLT_MAX;
            colpos[t] = -FLT_MAX; colneg[t] = FLT_MAX;
        }
        #pragma unroll
        for (int mi = 0; mi < 8; mi++) {
            const int gi = rowBase + m0 + mi;
            #pragma unroll
            for (int nj = 0; nj < 4; nj++) {
                float c0, c1;
                unpack2(acc[mi][nj], c0, c1);
                #pragma unroll
                for (int h = 0; h < 2; h++) {
                    const int   nn = nj * 2 + h;
                    const float c  = h ? c1 : c0;
                    float d2 = fmaxf(sqi[mi] + sqj[nn] - 2.0f * c, 0.0f);
                    const int gj = colBase + n0 + nn;
                    if (li[mi] == lj[nn]) {
                        if (gi != gj) {
                            posmax[mi] = fmaxf(posmax[mi], d2);
                            colpos[nn] = fmaxf(colpos[nn], d2);
                        }
                    } else {
                        negmin[mi] = fminf(negmin[mi], d2);
                        colneg[nn] = fminf(colneg[nn], d2);
                    }
                }
            }
        }
        #pragma unroll
        for (int mi = 0; mi < 8; mi++) {
            #pragma unroll
            for (int o = 1; o < 16; o <<= 1) {
                posmax[mi] = fmaxf(posmax[mi], __shfl_xor_sync(0xffffffffu, posmax[mi], o));
                negmin[mi] = fminf(negmin[mi], __shfl_xor_sync(0xffffffffu, negmin[mi], o));
            }
        }
        if (tx == 0) {
            #pragma unroll
            for (int mi = 0; mi < 8; mi++) {
                atomicMax(&g_pos[rowBase + m0 + mi], f2ord(posmax[mi]));
                atomicMin(&g_neg[rowBase + m0 + mi], f2ord(negmin[mi]));
            }
        }
        if (I != J) {
            float* red = Bs;
            __syncthreads();
            #pragma unroll
            for (int h = 0; h < 8; h++) red[(n0 + h) * 17 + ty] = colpos[h];
            __syncthreads();
            if (tid < 128) {
                float v = -FLT_MAX;
                #pragma unroll
                for (int t = 0; t < 16; t++) v = fmaxf(v, red[tid * 17 + t]);
                atomicMax(&g_pos[colBase + tid], f2ord(v));
            }
            __syncthreads();
            #pragma unroll
            for (int h = 0; h < 8; h++) red[(n0 + h) * 17 + ty] = colneg[h];
            __syncthreads();
            if (tid < 128) {
                float v = FLT_MAX;
                #pragma unroll
                for (int t = 0; t < 16; t++) v = fminf(v, red[tid * 17 + t]);
                atomicMin(&g_neg[colBase + tid], f2ord(v));
            }
        }
        __syncthreads();
    }
#endif
}

// ---------------------------------------------------------------------------
// Kernel 3a: parallel finalize — one thread per row, warp-reduce, atomics.
// ---------------------------------------------------------------------------
__global__ void finalize_partial() {
    const int r   = blockIdx.x * 256 + threadIdx.x;
    const int lid = threadIdx.x & 31;
    const float p2 = ord2f(g_pos[r]);
    const float n2 = ord2f(g_neg[r]);
    float s = 0.0f;
    int   c = 0;
    if (p2 != -FLT_MAX && n2 != FLT_MAX) {
        const float pr = sqrtf(fmaxf(p2, 0.0f)) - sqrtf(fmaxf(n2, 0.0f)) + MARGIN_F;
        if (pr > 0.0f) s = pr;
        c = 1;
    }
    #pragma unroll
    for (int o = 16; o; o >>= 1) {
        s += __shfl_xor_sync(0xffffffffu, s, o);
        c += __shfl_xor_sync(0xffffffffu, c, o);
    }
    if (lid == 0) {
        atomicAdd(&g_sum, s);
        atomicAdd(&g_cnt, c);
    }
}

// Kernel 3b: single-thread division.
__global__ void finalize_write(float* __restrict__ out) {
    const int cnt = g_cnt > 1 ? g_cnt : 1;
    out[0] = g_sum / (float)cnt;
}

extern "C" void kernel_launch(void* const* d_in, const int* in_sizes, int n_in,
                              void* d_out, int out_size) {
    const float* X   = (const float*)d_in[0];
    const int*   lab = (const int*)d_in[1];   // JAX x64 disabled -> int32 labels

    split_kernel<<<NT, 256>>>(X);

    cudaFuncSetAttribute(pair_kernel, cudaFuncAttributeMaxDynamicSharedMemorySize, SMEM_TOTAL);
    pair_kernel<<<GRID_PERS, 256, SMEM_TOTAL>>>(X, lab);

    finalize_partial<<<NROWS / 256, 256>>>();
    finalize_write<<<1, 1>>>((float*)d_out);
}

// round 16
// speedup vs baseline: 1.0648x; 1.0648x over previous
#include <cuda_runtime.h>
#include <cuda_bf16.h>
#include <float.h>
#include <cstdint>

#define NROWS 8192
#define DIM   128
#define NT    64
#define NPAIR (NT*(NT+1)/2)   // 2080 triangular tile pairs
#define GRID_PERS 148
#define MARGIN_F 0.5f

// smem map (tcgen05 path)
#define CTRL_TMEM   0
#define CTRL_MBTMA  8
#define CTRL_MBMMA1 16
#define CTRL_MBMMA2 24
#define CTRL_SQI    128
#define CTRL_SQJ    640
#define CTRL_LABI   1152
#define CTRL_LABJ   1664
#define REGION0     4096
#define REG_SZ      32768
#define SMEM_TOTAL  (REGION0 + 4 * REG_SZ)   // 135168 B

// idesc kind::f16 cg1: F32 out, BF16 a/b, N=128, M=128
#define MMA_IDESC 0x8200490u

// fallback (plain sm_103) FFMA tiling constants
#define BK    32
#define LDA2  130
#define LDB   132

#if defined(__CUDA_ARCH_FEAT_SM103_ALL) || defined(__CUDA_ARCH_FEAT_SM100_ALL)
#define HAS_TCGEN05 1
#else
#define HAS_TCGEN05 0
#endif

typedef unsigned long long ull;

__device__ int   g_pos[NROWS];
__device__ int   g_neg[NROWS];
__device__ float g_sq[NROWS];
__device__ float g_sum;
__device__ int   g_cnt;
// Pre-split bf16 tiles in blocked SW128 layout: 64 tiles x 32KB each.
__device__ __align__(128) ull g_hi[NT * 4096];
__device__ __align__(128) ull g_lo[NT * 4096];

__device__ __forceinline__ int f2ord(float f) {
    int i = __float_as_int(f);
    return i >= 0 ? i : i ^ 0x7FFFFFFF;
}
__device__ __forceinline__ float ord2f(int i) {
    return __int_as_float(i >= 0 ? i : i ^ 0x7FFFFFFF);
}
__device__ __forceinline__ ull pack4(unsigned short a, unsigned short b,
                                     unsigned short c, unsigned short d) {
    return (ull)a | ((ull)b << 16) | ((ull)c << 32) | ((ull)d << 48);
}
__device__ __forceinline__ void split2(float x, unsigned short &h, unsigned short &l) {
    __nv_bfloat16 a = __float2bfloat16(x);
    __nv_bfloat16 b = __float2bfloat16(x - __bfloat162float(a));
    h = __bfloat16_as_ushort(a);
    l = __bfloat16_as_ushort(b);
}

// ---------------------------------------------------------------------------
// Kernel 1 (merged): 2-way bf16 split of X into pre-swizzled blocked-SW128
// tiles AND row squared norms + accumulator init. Warp-per-row layout: for
// each strided iteration, one warp covers one row (lane = 4-col group).
// ---------------------------------------------------------------------------
__global__ void split_kernel(const float* __restrict__ X) {
    const int t = blockIdx.x;
    const float* src = X + (size_t)t * 128 * DIM;
    char* hi = (char*)g_hi + (size_t)t * REG_SZ;
    char* lo = (char*)g_lo + (size_t)t * REG_SZ;
    if (t == 0 && threadIdx.x == 0) { g_sum = 0.0f; g_cnt = 0; }
    for (int f = threadIdx.x; f < 4096; f += 256) {
        int row = f >> 5, c4 = f & 31;
        float4 v = reinterpret_cast<const float4*>(src + (size_t)row * DIM)[c4];
        int col  = c4 * 4;
        int boff = ((row >> 3) + (col >> 6) * 16) * 1024 + (row & 7) * 128 + (col & 63) * 2;
        int sw   = boff ^ ((boff >> 3) & 0x70);
        unsigned short h0,l0, h1,l1, h2,l2, h3,l3;
        split2(v.x, h0, l0); split2(v.y, h1, l1);
        split2(v.z, h2, l2); split2(v.w, h3, l3);
        *(ull*)(hi + sw) = pack4(h0, h1, h2, h3);
        *(ull*)(lo + sw) = pack4(l0, l1, l2, l3);
        // Row norm: whole warp holds this row (lane == c4).
        float s = v.x * v.x + v.y * v.y + v.z * v.z + v.w * v.w;
        #pragma unroll
        for (int o = 16; o; o >>= 1) s += __shfl_xor_sync(0xffffffffu, s, o);
        if (c4 == 0) {
            int grow = t * 128 + row;
            g_sq[grow]  = s;
            g_pos[grow] = f2ord(-FLT_MAX);
            g_neg[grow] = f2ord(FLT_MAX);
        }
    }
}

#if HAS_TCGEN05
// ============================ tcgen05 path ==================================
__device__ __forceinline__ uint32_t smem_u32(const void* p) {
    uint32_t a;
    asm("{ .reg .u64 t; cvta.to.shared.u64 t, %1; cvt.u32.u64 %0, t; }" : "=r"(a) : "l"(p));
    return a;
}
__device__ __forceinline__ uint32_t elect_one_pred() {
    uint32_t p;
    asm volatile("{ .reg .pred p; elect.sync _|p, 0xFFFFFFFF; selp.b32 %0, 1, 0, p; }" : "=r"(p));
    return p;
}
#define TCGEN05_ALLOC(smaddr, n) \
    asm volatile("tcgen05.alloc.cta_group::1.sync.aligned.shared::cta.b32 [%0], %1;" \
                 :: "r"((uint32_t)(smaddr)), "r"((uint32_t)(n)) : "memory")
#define TCGEN05_DEALLOC(tm, n) \
    asm volatile("tcgen05.dealloc.cta_group::1.sync.aligned.b32 %0, %1;" :: "r"(tm), "r"((uint32_t)(n)))
#define TCGEN05_COMMIT(mb) \
    asm volatile("tcgen05.commit.cta_group::1.mbarrier::arrive::one.shared::cluster.b64 [%0];" \
                 :: "r"((uint32_t)(mb)) : "memory")
#define TCGEN05_FENCE_AFTER()  asm volatile("tcgen05.fence::after_thread_sync;" ::: "memory")
#define TCGEN05_FENCE_BEFORE() asm volatile("tcgen05.fence::before_thread_sync;" ::: "memory")
#define TCGEN05_WAIT_LD()      asm volatile("tcgen05.wait::ld.sync.aligned;" ::: "memory")
#define MBARRIER_INIT(mb, n) \
    asm volatile("mbarrier.init.shared.b64 [%0], %1;" :: "r"((uint32_t)(mb)), "r"((uint32_t)(n)) : "memory")
#define MBARRIER_INVAL(mb) \
    asm volatile("mbarrier.inval.shared.b64 [%0];" :: "r"((uint32_t)(mb)) : "memory")
#define MBARRIER_EXPECT_TX(mb, bytes) \
    asm volatile("mbarrier.arrive.expect_tx.shared.b64 _, [%0], %1;" \
                 :: "r"((uint32_t)(mb)), "r"((uint32_t)(bytes)) : "memory")
#define MBARRIER_WAIT_PARITY(mb, ph) do {                                        \
    uint32_t _mb = (uint32_t)(mb), _ph = (uint32_t)(ph), _done;                  \
    asm volatile("{ .reg .pred p; mbarrier.try_wait.parity.acquire.cta.shared::cta.b64 p, [%1], %2;" \
                 " selp.b32 %0, 1, 0, p; }" : "=r"(_done) : "r"(_mb), "r"(_ph) : "memory"); \
    if (!_done) {                                                                \
        asm volatile("{ .reg .pred P1; WL_%=:"                                   \
                     " mbarrier.try_wait.parity.acquire.cta.shared::cta.b64 P1, [%0], %1, 0x989680;" \
                     " @P1 bra.uni WD_%=; bra.uni WL_%=; WD_%=: }"               \
                     :: "r"(_mb), "r"(_ph) : "memory");                          \
    }                                                                            \
} while (0)
#define BULK_G2S(dst, src, bytes, mb) \
    asm volatile("cp.async.bulk.shared::cta.global.mbarrier::complete_tx::bytes [%0], [%1], %2, [%3];" \
                 :: "r"((uint32_t)(dst)), "l"(src), "r"((uint32_t)(bytes)), "r"((uint32_t)(mb)) : "memory")
#define TCGEN05_LD_32X32B_X32(r, tm) \
    asm volatile("tcgen05.ld.sync.aligned.32x32b.x32.b32 " \
        "{%0, %1, %2, %3, %4, %5, %6, %7, %8, %9, %10, %11, %12, %13, %14, %15, " \
        " %16, %17, %18, %19, %20, %21, %22, %23, %24, %25, %26, %27, %28, %29, %30, %31}, [%32];" \
        : "=r"((r)[0]),  "=r"((r)[1]),  "=r"((r)[2]),  "=r"((r)[3]), \
          "=r"((r)[4]),  "=r"((r)[5]),  "=r"((r)[6]),  "=r"((r)[7]), \
          "=r"((r)[8]),  "=r"((r)[9]),  "=r"((r)[10]), "=r"((r)[11]), \
          "=r"((r)[12]), "=r"((r)[13]), "=r"((r)[14]), "=r"((r)[15]), \
          "=r"((r)[16]), "=r"((r)[17]), "=r"((r)[18]), "=r"((r)[19]), \
          "=r"((r)[20]), "=r"((r)[21]), "=r"((r)[22]), "=r"((r)[23]), \
          "=r"((r)[24]), "=r"((r)[25]), "=r"((r)[26]), "=r"((r)[27]), \
          "=r"((r)[28]), "=r"((r)[29]), "=r"((r)[30]), "=r"((r)[31]) \
        : "r"(tm))

static constexpr uint64_t SMEM_DESC_BASE_SW128 =
    (uint64_t(2) << 61) | (uint64_t(1) << 46) | (uint64_t(64) << 32) | (uint64_t(1) << 16);
#define MAKE_SMEM_DESC(a) (SMEM_DESC_BASE_SW128 | ((uint64_t)((a) >> 4) & 0x3FFF))

__device__ __forceinline__ void mma_f16_ss(uint32_t d, uint64_t a, uint64_t b,
                                           uint32_t idesc, uint32_t accum) {
    asm volatile(
        "{ .reg .pred p; setp.ne.u32 p, %5, 0;\n\t"
        "tcgen05.mma.cta_group::1.kind::f16 [%0], %1, %2, %3, {%4, %4, %4, %4}, p; }"
        :: "r"(d), "l"(a), "l"(b), "r"(idesc), "r"(0u), "r"(accum) : "memory");
}

// One GEMM: 3 split-terms (hh, hl, lh) x 8 K-steps of 128x128x16 bf16 MMA.
__device__ __forceinline__ void issue_gemm(uint32_t d, uint64_t ah, uint64_t al,
                                           uint64_t bh, uint64_t bl) {
    const uint64_t A[3] = {ah, ah, al};
    const uint64_t B[3] = {bh, bl, bh};
    uint32_t accum = 0;
    #pragma unroll
    for (int t = 0; t < 3; t++) {
        #pragma unroll
        for (int k = 0; k < 8; k++) {
            uint64_t off = (k < 4) ? (uint64_t)(2 * k) : (uint64_t)(1024 + 2 * (k - 4));
            mma_f16_ss(d, A[t] + off, B[t] + off, MMA_IDESC, accum);
            accum = 1;
        }
    }
}

// Row-local epilogue over one 128x128 D tile (d^2 tracking, no sqrt).
__device__ __forceinline__ void process_tile(uint32_t tmem_d, int rowBaseX, int colBaseX,
                                             const float* sqRow, const int* labRow,
                                             const float* sqCol, const int* labCol,
                                             int wid, int lid) {
    const int sub = wid & 3, half = wid >> 2;
    const int r = sub * 32 + lid;
    uint32_t regs[64];
    TCGEN05_LD_32X32B_X32(regs,      tmem_d + half * 64);
    TCGEN05_LD_32X32B_X32(regs + 32, tmem_d + half * 64 + 32);
    TCGEN05_WAIT_LD();
    const float sqr = sqRow[r];
    const int   lr  = labRow[r];
    const int   gi  = rowBaseX + r;
    float pmax = -FLT_MAX, nmin = FLT_MAX;
    #pragma unroll 8
    for (int c = 0; c < 64; c++) {
        const int col = half * 64 + c;
        const float dot = __uint_as_float(regs[c]);
        float d2 = fmaxf(sqr + sqCol[col] - 2.0f * dot, 0.0f);
        const int gj = colBaseX + col;
        if (lr == labCol[col]) {
            if (gi != gj) pmax = fmaxf(pmax, d2);
        } else {
            nmin = fminf(nmin, d2);
        }
    }
    atomicMax(&g_pos[gi], f2ord(pmax));
    atomicMin(&g_neg[gi], f2ord(nmin));
}
#else
// ============================ FFMA fallback helpers =========================
__device__ __forceinline__ ull dup2(float x) {
    ull r; asm("mov.b64 %0, {%1, %1};" : "=l"(r) : "f"(x)); return r;
}
__device__ __forceinline__ void fma2(ull &d, ull a, ull b) {
    asm("fma.rn.f32x2 %0, %1, %2, %0;" : "+l"(d) : "l"(a), "l"(b));
}
__device__ __forceinline__ void unpack2(ull v, float &x, float &y) {
    asm("mov.b64 {%0, %1}, %2;" : "=f"(x), "=f"(y) : "l"(v));
}
#endif

__device__ __forceinline__ void decode_pair(int p, int &I, int &J) {
    int idx = p, i = 0, len = NT;
    while (idx >= len) { idx -= len; i++; len--; }
    I = i; J = i + idx;
}

// ---------------------------------------------------------------------------
// Kernel 2: persistent CTAs, pipelined. Each iteration: one 128x128 tile pair
// (I,J), J>=I. sm_103a: bulk-copied pre-split bf16 tiles + tcgen05 GEMM of
// D=X_I.X_J^T and D^T with SPLIT commits: epilogue(D1) overlaps MMA(D2);
// next pair's TMA flies under epilogue(D2).
// ---------------------------------------------------------------------------
__global__ __launch_bounds__(256, 1)
void pair_kernel(const float* __restrict__ X, const int* __restrict__ lab) {
    extern __shared__ char sm[];
    const int tid = threadIdx.x;

#if HAS_TCGEN05
    const uint32_t smb = smem_u32(sm);
    const int wid = tid >> 5, lid = tid & 31;

    if (wid == 0) TCGEN05_ALLOC(smb + CTRL_TMEM, 256);
    if (tid == 0) {
        MBARRIER_INIT(smb + CTRL_MBTMA, 1);
        MBARRIER_INIT(smb + CTRL_MBMMA1, 1);
        MBARRIER_INIT(smb + CTRL_MBMMA2, 1);
    }
    __syncthreads();

    uint32_t tmem;
    asm volatile("ld.shared.b32 %0, [%1];" : "=r"(tmem) : "r"(smb + CTRL_TMEM));
    const uint32_t D1 = tmem, D2 = tmem + 128;

    const uint64_t dAh = MAKE_SMEM_DESC(smb + REGION0 + 0 * REG_SZ);
    const uint64_t dAl = MAKE_SMEM_DESC(smb + REGION0 + 1 * REG_SZ);
    const uint64_t dBh = MAKE_SMEM_DESC(smb + REGION0 + 2 * REG_SZ);
    const uint64_t dBl = MAKE_SMEM_DESC(smb + REGION0 + 3 * REG_SZ);

    float* sqI = (float*)(sm + CTRL_SQI);
    float* sqJ = (float*)(sm + CTRL_SQJ);
    int*   lbI = (int*)(sm + CTRL_LABI);
    int*   lbJ = (int*)(sm + CTRL_LABJ);

    int ph_tma = 0, ph_mma = 0;

    // Prologue: issue copies for first pair.
    if (tid == 0) {
        int I0, J0; decode_pair(blockIdx.x, I0, J0);
        MBARRIER_EXPECT_TX(smb + CTRL_MBTMA, 4 * REG_SZ);
        BULK_G2S(smb + REGION0 + 0 * REG_SZ, (const void*)(g_hi + (size_t)I0 * 4096), REG_SZ, smb + CTRL_MBTMA);
        BULK_G2S(smb + REGION0 + 1 * REG_SZ, (const void*)(g_lo + (size_t)I0 * 4096), REG_SZ, smb + CTRL_MBTMA);
        BULK_G2S(smb + REGION0 + 2 * REG_SZ, (const void*)(g_hi + (size_t)J0 * 4096), REG_SZ, smb + CTRL_MBTMA);
        BULK_G2S(smb + REGION0 + 3 * REG_SZ, (const void*)(g_lo + (size_t)J0 * 4096), REG_SZ, smb + CTRL_MBTMA);
    }

    for (int p = blockIdx.x; p < NPAIR; p += GRID_PERS) {
        int I, J; decode_pair(p, I, J);
        const int rowBase = I * 128, colBase = J * 128;

        // Stage norms/labels early (CTRL region, independent of TMA/MMA;
        // loop-end __syncthreads guarantees last epilogue is done reading).
        if (tid < 128) {
            sqI[tid] = g_sq[rowBase + tid];
            sqJ[tid] = g_sq[colBase + tid];
            lbI[tid] = lab[rowBase + tid];
            lbJ[tid] = lab[colBase + tid];
        }

        // MMA issue (warp 0) after tile data lands; split commits.
        if (wid == 0) {
            MBARRIER_WAIT_PARITY(smb + CTRL_MBTMA, ph_tma);
            TCGEN05_FENCE_AFTER();
            if (elect_one_pred()) {
                issue_gemm(D1, dAh, dAl, dBh, dBl);   // X_I . X_J^T
                TCGEN05_COMMIT(smb + CTRL_MBMMA1);
                issue_gemm(D2, dBh, dBl, dAh, dAl);   // X_J . X_I^T
                TCGEN05_COMMIT(smb + CTRL_MBMMA2);
            }
        }
        ph_tma ^= 1;

        // D1 ready while D2's MMA still runs.
        MBARRIER_WAIT_PARITY(smb + CTRL_MBMMA1, ph_mma);
        __syncthreads();          // norms/labels staged & visible to all
        TCGEN05_FENCE_AFTER();
        process_tile(D1, rowBase, colBase, sqI, lbI, sqJ, lbJ, wid, lid);

        // D2 done => smem tile buffers free: prefetch next pair now.
        MBARRIER_WAIT_PARITY(smb + CTRL_MBMMA2, ph_mma);
        ph_mma ^= 1;
        if (p + GRID_PERS < NPAIR && tid == 0) {
            int In, Jn; decode_pair(p + GRID_PERS, In, Jn);
            MBARRIER_EXPECT_TX(smb + CTRL_MBTMA, 4 * REG_SZ);
            BULK_G2S(smb + REGION0 + 0 * REG_SZ, (const void*)(g_hi + (size_t)In * 4096), REG_SZ, smb + CTRL_MBTMA);
            BULK_G2S(smb + REGION0 + 1 * REG_SZ, (const void*)(g_lo + (size_t)In * 4096), REG_SZ, smb + CTRL_MBTMA);
            BULK_G2S(smb + REGION0 + 2 * REG_SZ, (const void*)(g_hi + (size_t)Jn * 4096), REG_SZ, smb + CTRL_MBTMA);
            BULK_G2S(smb + REGION0 + 3 * REG_SZ, (const void*)(g_lo + (size_t)Jn * 4096), REG_SZ, smb + CTRL_MBTMA);
        }

        TCGEN05_FENCE_AFTER();
        process_tile(D2, colBase, rowBase, sqJ, lbJ, sqI, lbI, wid, lid);
        TCGEN05_FENCE_BEFORE();
        __syncthreads();   // epilogue done before next iteration's MMA writes D
    }

    __syncthreads();
    if (tid == 0) {
        MBARRIER_INVAL(smb + CTRL_MBTMA);
        MBARRIER_INVAL(smb + CTRL_MBMMA1);
        MBARRIER_INVAL(smb + CTRL_MBMMA2);
    }
    __syncthreads();
    if (wid == 0) TCGEN05_DEALLOC(tmem, 256);

#else
    // -------- f32x2 FFMA fallback (persistent, d^2 tracking) ----------------
    ull*   As2 = (ull*)sm;                        // [BK][LDA2]
    float* Bs  = (float*)(As2 + BK * LDA2);       // [BK][LDB]
    const int tx = tid & 15, ty = tid >> 4;
    const int m0 = ty * 8, n0 = tx * 8;

    for (int p = blockIdx.x; p < NPAIR; p += GRID_PERS) {
        int I, J; decode_pair(p, I, J);
        const int rowBase = I * 128, colBase = J * 128;

        ull acc[8][4];
        #pragma unroll
        for (int mi = 0; mi < 8; mi++)
            #pragma unroll
            for (int nj = 0; nj < 4; nj++) acc[mi][nj] = 0ull;

        for (int kb = 0; kb < DIM; kb += BK) {
            __syncthreads();
            for (int i = tid; i < 128 * (BK / 4); i += 256) {
                int r = i >> 3, c4 = i & 7;
                float4 v = reinterpret_cast<const float4*>(
                    X + (size_t)(rowBase + r) * DIM + kb)[c4];
                int k = c4 * 4;
                As2[(k + 0) * LDA2 + r] = dup2(v.x);
                As2[(k + 1) * LDA2 + r] = dup2(v.y);
                As2[(k + 2) * LDA2 + r] = dup2(v.z);
                As2[(k + 3) * LDA2 + r] = dup2(v.w);
            }
            for (int i = tid; i < 128 * (BK / 4); i += 256) {
                int n = i >> 3, c4 = i & 7;
                float4 v = reinterpret_cast<const float4*>(
                    X + (size_t)(colBase + n) * DIM + kb)[c4];
                int k = c4 * 4;
                Bs[(k + 0) * LDB + n] = v.x;
                Bs[(k + 1) * LDB + n] = v.y;
                Bs[(k + 2) * LDB + n] = v.z;
                Bs[(k + 3) * LDB + n] = v.w;
            }
            __syncthreads();
            #pragma unroll 8
            for (int k = 0; k < BK; k++) {
                const ull* arow = &As2[k * LDA2 + m0];
                const ull* brow = (const ull*)&Bs[k * LDB + n0];
                ull A2[8], B2[4];
                #pragma unroll
                for (int t = 0; t < 8; t++) A2[t] = arow[t];
                #pragma unroll
                for (int t = 0; t < 4; t++) B2[t] = brow[t];
                #pragma unroll
                for (int mi = 0; mi < 8; mi++)
                    #pragma unroll
                    for (int nj = 0; nj < 4; nj++)
                        fma2(acc[mi][nj], A2[mi], B2[nj]);
            }
        }

        float sqi[8]; int li[8]; float sqj[8]; int lj[8];
        #pragma unroll
        for (int t = 0; t < 8; t++) {
            sqi[t] = g_sq[rowBase + m0 + t];  li[t] = lab[rowBase + m0 + t];
            sqj[t] = g_sq[colBase + n0 + t];  lj[t] = lab[colBase + n0 + t];
        }
        float posmax[8], negmin[8], colpos[8], colneg[8];
        #pragma unroll
        for (int t = 0; t < 8; t++) {
            posmax[t] = -FLT_MAX; negmin[t] = FLT_MAX;
            colpos[t] = -FLT_MAX; colneg[t] = FLT_MAX;
        }
        #pragma unroll
        for (int mi = 0; mi < 8; mi++) {
            const int gi = rowBase + m0 + mi;
            #pragma unroll
            for (int nj = 0; nj < 4; nj++) {
                float c0, c1;
                unpack2(acc[mi][nj], c0, c1);
                #pragma unroll
                for (int h = 0; h < 2; h++) {
                    const int   nn = nj * 2 + h;
                    const float c  = h ? c1 : c0;
                    float d2 = fmaxf(sqi[mi] + sqj[nn] - 2.0f * c, 0.0f);
                    const int gj = colBase + n0 + nn;
                    if (li[mi] == lj[nn]) {
                        if (gi != gj) {
                            posmax[mi] = fmaxf(posmax[mi], d2);
                            colpos[nn] = fmaxf(colpos[nn], d2);
                        }
                    } else {
                        negmin[mi] = fminf(negmin[mi], d2);
                        colneg[nn] = fminf(colneg[nn], d2);
                    }
                }
            }
        }
        #pragma unroll
        for (int mi = 0; mi < 8; mi++) {
            #pragma unroll
            for (int o = 1; o < 16; o <<= 1) {
                posmax[mi] = fmaxf(posmax[mi], __shfl_xor_sync(0xffffffffu, posmax[mi], o));
                negmin[mi] = fminf(negmin[mi], __shfl_xor_sync(0xffffffffu, negmin[mi], o));
            }
        }
        if (tx == 0) {
            #pragma unroll
            for (int mi = 0; mi < 8; mi++) {
                atomicMax(&g_pos[rowBase + m0 + mi], f2ord(posmax[mi]));
                atomicMin(&g_neg[rowBase + m0 + mi], f2ord(negmin[mi]));
            }
        }
        if (I != J) {
            float* red = Bs;
            __syncthreads();
            #pragma unroll
            for (int h = 0; h < 8; h++) red[(n0 + h) * 17 + ty] = colpos[h];
            __syncthreads();
            if (tid < 128) {
                float v = -FLT_MAX;
                #pragma unroll
                for (int t = 0; t < 16; t++) v = fmaxf(v, red[tid * 17 + t]);
                atomicMax(&g_pos[colBase + tid], f2ord(v));
            }
            __syncthreads();
            #pragma unroll
            for (int h = 0; h < 8; h++) red[(n0 + h) * 17 + ty] = colneg[h];
            __syncthreads();
            if (tid < 128) {
                float v = FLT_MAX;
                #pragma unroll
                for (int t = 0; t < 16; t++) v = fminf(v, red[tid * 17 + t]);
                atomicMin(&g_neg[colBase + tid], f2ord(v));
            }
        }
        __syncthreads();
    }
#endif
}

// ---------------------------------------------------------------------------
// Kernel 3a: parallel finalize — one thread per row, warp-reduce, atomics.
// ---------------------------------------------------------------------------
__global__ void finalize_partial() {
    const int r   = blockIdx.x * 256 + threadIdx.x;
    const int lid = threadIdx.x & 31;
    const float p2 = ord2f(g_pos[r]);
    const float n2 = ord2f(g_neg[r]);
    float s = 0.0f;
    int   c = 0;
    if (p2 != -FLT_MAX && n2 != FLT_MAX) {
        const float pr = sqrtf(fmaxf(p2, 0.0f)) - sqrtf(fmaxf(n2, 0.0f)) + MARGIN_F;
        if (pr > 0.0f) s = pr;
        c = 1;
    }
    #pragma unroll
    for (int o = 16; o; o >>= 1) {
        s += __shfl_xor_sync(0xffffffffu, s, o);
        c += __shfl_xor_sync(0xffffffffu, c, o);
    }
    if (lid == 0) {
        atomicAdd(&g_sum, s);
        atomicAdd(&g_cnt, c);
    }
}

// Kernel 3b: single-thread division.
__global__ void finalize_write(float* __restrict__ out) {
    const int cnt = g_cnt > 1 ? g_cnt : 1;
    out[0] = g_sum / (float)cnt;
}

extern "C" void kernel_launch(void* const* d_in, const int* in_sizes, int n_in,
                              void* d_out, int out_size) {
    const float* X   = (const float*)d_in[0];
    const int*   lab = (const int*)d_in[1];   // JAX x64 disabled -> int32 labels

    split_kernel<<<NT, 256>>>(X);

    cudaFuncSetAttribute(pair_kernel, cudaFuncAttributeMaxDynamicSharedMemorySize, SMEM_TOTAL);
    pair_kernel<<<GRID_PERS, 256, SMEM_TOTAL>>>(X, lab);

    finalize_partial<<<NROWS / 256, 256>>>();
    finalize_write<<<1, 1>>>((float*)d_out);
}